// round 1
// baseline (speedup 1.0000x reference)
#include <cuda_runtime.h>
#include <cstdint>

#define NPTS  100000
#define KVOL  27
#define PAIRS 60000
#define CCH   64
#define TP    128
#define NTILES ((PAIRS + TP - 1) / TP)

// dynamic smem: W (64*64 f32) + Xt (64*128 f32) + in/out map tiles (2*128 i32)
#define SMEM_FLOATS (CCH*CCH + CCH*TP)
#define SMEM_BYTES  (SMEM_FLOATS*4 + 2*TP*4)

#define FMA2(acc, a, b) \
    asm("fma.rn.f32x2 %0, %1, %2, %0;" : "+l"(acc) : "l"(a), "l"(b))

__global__ void __launch_bounds__(256) init_bias_kernel(
    const float* __restrict__ bias, float* __restrict__ out)
{
    int idx = blockIdx.x * 256 + threadIdx.x;
    if (idx < NPTS * CCH) out[idx] = bias[idx & (CCH - 1)];
}

__global__ void __launch_bounds__(256) sparse_conv_kernel(
    const float* __restrict__ input,
    const float* __restrict__ kernel,
    const int*   __restrict__ in_map,
    const int*   __restrict__ out_map,
    float*       __restrict__ out)
{
    extern __shared__ float smem[];
    float* sW  = smem;                   // [64][64]
    float* sX  = smem + CCH * CCH;       // [64][128]  transposed: sX[i*TP + p]
    int*   sIn = (int*)(smem + SMEM_FLOATS);
    int*   sOut = sIn + TP;

    const int k    = blockIdx.y;
    const int base = blockIdx.x * TP;
    const int tid  = threadIdx.x;
    const int nrem = min(TP, PAIRS - base);

    // stage pair maps (coalesced)
    if (tid < TP) {
        if (tid < nrem) {
            sIn[tid]  = in_map [k * PAIRS + base + tid];
            sOut[tid] = out_map[k * PAIRS + base + tid];
        } else {
            sIn[tid] = -1;
            sOut[tid] = -1;
        }
    }
    // stage W_k (16 KB, float4)
    {
        const float4* Wg = (const float4*)(kernel + k * CCH * CCH);
        float4* Ws = (float4*)sW;
        #pragma unroll
        for (int s = 0; s < 4; s++) Ws[tid + 256 * s] = Wg[tid + 256 * s];
    }
    __syncthreads();

    // gather: 128 rows x 64 f32, store transposed, p-fastest within warp
    // (conflict-free STS: lanes hit banks p..p+31)
    #pragma unroll
    for (int s = 0; s < 8; s++) {
        int m = tid + 256 * s;
        int p = m & (TP - 1);
        int j = m >> 7;                       // 16B chunk 0..15
        int row = sIn[p];
        float4 v = make_float4(0.f, 0.f, 0.f, 0.f);
        if (row >= 0) v = ((const float4*)input)[row * (CCH / 4) + j];
        sX[(4 * j + 0) * TP + p] = v.x;
        sX[(4 * j + 1) * TP + p] = v.y;
        sX[(4 * j + 2) * TP + p] = v.z;
        sX[(4 * j + 3) * TP + p] = v.w;
    }
    __syncthreads();

    // GEMM: Y[128x64] = X[128x64] @ W[64x64]
    // 256 threads = 16(ty, rows) x 16(tx, cols); micro-tile 8 rows x 4 cols,
    // rows packed pairwise into f32x2 accumulators.
    const int tx = tid & 15;
    const int ty = tid >> 4;

    unsigned long long acc[4][4];
    #pragma unroll
    for (int r = 0; r < 4; r++)
        #pragma unroll
        for (int c = 0; c < 4; c++) acc[r][c] = 0ULL;

    unsigned xaddr = (unsigned)__cvta_generic_to_shared(sX + ty * 8);
    unsigned waddr = (unsigned)__cvta_generic_to_shared(sW + tx * 4);

    #pragma unroll 8
    for (int i = 0; i < CCH; i++) {
        unsigned long long a0, a1, a2, a3;   // row pairs (p,p+1) packed f32x2
        asm("ld.shared.v2.b64 {%0,%1}, [%2];"
            : "=l"(a0), "=l"(a1) : "r"(xaddr));
        asm("ld.shared.v2.b64 {%0,%1}, [%2];"
            : "=l"(a2), "=l"(a3) : "r"(xaddr + 16));
        unsigned b0, b1, b2, b3;
        asm("ld.shared.v4.b32 {%0,%1,%2,%3}, [%4];"
            : "=r"(b0), "=r"(b1), "=r"(b2), "=r"(b3) : "r"(waddr));
        unsigned long long bb0, bb1, bb2, bb3;
        asm("mov.b64 %0, {%1,%1};" : "=l"(bb0) : "r"(b0));
        asm("mov.b64 %0, {%1,%1};" : "=l"(bb1) : "r"(b1));
        asm("mov.b64 %0, {%1,%1};" : "=l"(bb2) : "r"(b2));
        asm("mov.b64 %0, {%1,%1};" : "=l"(bb3) : "r"(b3));

        FMA2(acc[0][0], a0, bb0); FMA2(acc[0][1], a0, bb1);
        FMA2(acc[0][2], a0, bb2); FMA2(acc[0][3], a0, bb3);
        FMA2(acc[1][0], a1, bb0); FMA2(acc[1][1], a1, bb1);
        FMA2(acc[1][2], a1, bb2); FMA2(acc[1][3], a1, bb3);
        FMA2(acc[2][0], a2, bb0); FMA2(acc[2][1], a2, bb1);
        FMA2(acc[2][2], a2, bb2); FMA2(acc[2][3], a2, bb3);
        FMA2(acc[3][0], a3, bb0); FMA2(acc[3][1], a3, bb1);
        FMA2(acc[3][2], a3, bb2); FMA2(acc[3][3], a3, bb3);

        xaddr += TP * 4;
        waddr += CCH * 4;
    }

    // scatter-add (everything L2-resident)
    #pragma unroll
    for (int r = 0; r < 4; r++) {
        int p0 = ty * 8 + 2 * r;
        int o0 = sOut[p0];
        int o1 = sOut[p0 + 1];
        #pragma unroll
        for (int c = 0; c < 4; c++) {
            float lo = __uint_as_float((unsigned)(acc[r][c] & 0xffffffffULL));
            float hi = __uint_as_float((unsigned)(acc[r][c] >> 32));
            if (o0 >= 0) atomicAdd(out + o0 * CCH + tx * 4 + c, lo);
            if (o1 >= 0) atomicAdd(out + o1 * CCH + tx * 4 + c, hi);
        }
    }
}

extern "C" void kernel_launch(void* const* d_in, const int* in_sizes, int n_in,
                              void* d_out, int out_size)
{
    const float* input  = (const float*)d_in[0];
    const float* kern   = (const float*)d_in[1];
    const float* bias   = (const float*)d_in[2];
    const int*   in_map = (const int*)  d_in[3];
    const int*   out_map= (const int*)  d_in[4];
    float* out = (float*)d_out;

    cudaFuncSetAttribute(sparse_conv_kernel,
                         cudaFuncAttributeMaxDynamicSharedMemorySize, SMEM_BYTES);

    // out = bias (d_out is poisoned before timing)
    init_bias_kernel<<<(NPTS * CCH + 255) / 256, 256>>>(bias, out);

    dim3 grid(NTILES, KVOL);
    sparse_conv_kernel<<<grid, 256, SMEM_BYTES>>>(input, kern, in_map, out_map, out);
}

// round 2
// speedup vs baseline: 1.2463x; 1.2463x over previous
#include <cuda_runtime.h>
#include <cstdint>

#define NPTS  100000
#define KVOL  27
#define PAIRS 60000
#define CCH   64
#define TP    128
#define NTILES ((PAIRS + TP - 1) / TP)

// dynamic smem: W (64*64 f32) + Xt (64*128 f32) + in/out map tiles (2*128 i32)
#define SMEM_FLOATS (CCH*CCH + CCH*TP)
#define SMEM_BYTES  (SMEM_FLOATS*4 + 2*TP*4)

#define FMA2(acc, a, b) \
    asm("fma.rn.f32x2 %0, %1, %2, %0;" : "+l"(acc) : "l"(a), "l"(b))

#define RED_V4(ptr, x, y, z, w) \
    asm volatile("red.global.add.v4.f32 [%0], {%1,%2,%3,%4};" \
                 :: "l"(ptr), "f"(x), "f"(y), "f"(z), "f"(w) : "memory")

__global__ void __launch_bounds__(256) init_bias_kernel(
    const float* __restrict__ bias, float* __restrict__ out)
{
    int idx = blockIdx.x * 256 + threadIdx.x;
    if (idx < NPTS * CCH) out[idx] = bias[idx & (CCH - 1)];
}

__global__ void __launch_bounds__(256) sparse_conv_kernel(
    const float* __restrict__ input,
    const float* __restrict__ kernel,
    const int*   __restrict__ in_map,
    const int*   __restrict__ out_map,
    float*       __restrict__ out)
{
    extern __shared__ float smem[];
    float* sW  = smem;                   // [64][64]
    float* sX  = smem + CCH * CCH;       // [64][128]  transposed: sX[i*TP + p]
    int*   sIn = (int*)(smem + SMEM_FLOATS);
    int*   sOut = sIn + TP;

    const int k    = blockIdx.y;
    const int base = blockIdx.x * TP;
    const int tid  = threadIdx.x;
    const int nrem = min(TP, PAIRS - base);

    // stage pair maps (coalesced)
    if (tid < TP) {
        if (tid < nrem) {
            sIn[tid]  = in_map [k * PAIRS + base + tid];
            sOut[tid] = out_map[k * PAIRS + base + tid];
        } else {
            sIn[tid] = -1;
            sOut[tid] = -1;
        }
    }
    // stage W_k (16 KB, float4)
    {
        const float4* Wg = (const float4*)(kernel + k * CCH * CCH);
        float4* Ws = (float4*)sW;
        #pragma unroll
        for (int s = 0; s < 4; s++) Ws[tid + 256 * s] = Wg[tid + 256 * s];
    }
    __syncthreads();

    // gather: 128 rows x 64 f32, store transposed, p-fastest within warp
    #pragma unroll
    for (int s = 0; s < 8; s++) {
        int m = tid + 256 * s;
        int p = m & (TP - 1);
        int j = m >> 7;                       // 16B chunk 0..15
        int row = sIn[p];
        float4 v = make_float4(0.f, 0.f, 0.f, 0.f);
        if (row >= 0) v = ((const float4*)input)[row * (CCH / 4) + j];
        sX[(4 * j + 0) * TP + p] = v.x;
        sX[(4 * j + 1) * TP + p] = v.y;
        sX[(4 * j + 2) * TP + p] = v.z;
        sX[(4 * j + 3) * TP + p] = v.w;
    }
    __syncthreads();

    // GEMM: Y[128x64] = X[128x64] @ W[64x64]
    // 256 threads = 16(ty, rows) x 16(tx, cols); micro-tile 8 rows x 4 cols,
    // rows packed pairwise into f32x2 accumulators.
    const int tx = tid & 15;
    const int ty = tid >> 4;

    unsigned long long acc[4][4];
    #pragma unroll
    for (int r = 0; r < 4; r++)
        #pragma unroll
        for (int c = 0; c < 4; c++) acc[r][c] = 0ULL;

    unsigned xaddr = (unsigned)__cvta_generic_to_shared(sX + ty * 8);
    unsigned waddr = (unsigned)__cvta_generic_to_shared(sW + tx * 4);

    #pragma unroll 8
    for (int i = 0; i < CCH; i++) {
        unsigned long long a0, a1, a2, a3;   // row pairs (p,p+1) packed f32x2
        asm("ld.shared.v2.b64 {%0,%1}, [%2];"
            : "=l"(a0), "=l"(a1) : "r"(xaddr));
        asm("ld.shared.v2.b64 {%0,%1}, [%2];"
            : "=l"(a2), "=l"(a3) : "r"(xaddr + 16));
        unsigned b0, b1, b2, b3;
        asm("ld.shared.v4.b32 {%0,%1,%2,%3}, [%4];"
            : "=r"(b0), "=r"(b1), "=r"(b2), "=r"(b3) : "r"(waddr));
        unsigned long long bb0, bb1, bb2, bb3;
        asm("mov.b64 %0, {%1,%1};" : "=l"(bb0) : "r"(b0));
        asm("mov.b64 %0, {%1,%1};" : "=l"(bb1) : "r"(b1));
        asm("mov.b64 %0, {%1,%1};" : "=l"(bb2) : "r"(b2));
        asm("mov.b64 %0, {%1,%1};" : "=l"(bb3) : "r"(b3));

        FMA2(acc[0][0], a0, bb0); FMA2(acc[0][1], a0, bb1);
        FMA2(acc[0][2], a0, bb2); FMA2(acc[0][3], a0, bb3);
        FMA2(acc[1][0], a1, bb0); FMA2(acc[1][1], a1, bb1);
        FMA2(acc[1][2], a1, bb2); FMA2(acc[1][3], a1, bb3);
        FMA2(acc[2][0], a2, bb0); FMA2(acc[2][1], a2, bb1);
        FMA2(acc[2][2], a2, bb2); FMA2(acc[2][3], a2, bb3);
        FMA2(acc[3][0], a3, bb0); FMA2(acc[3][1], a3, bb1);
        FMA2(acc[3][2], a3, bb2); FMA2(acc[3][3], a3, bb3);

        xaddr += TP * 4;
        waddr += CCH * 4;
    }

    // scatter-add: one red.global.add.v4.f32 per (row, 4-col group).
    // Each thread owns cols tx*4..tx*4+3 of 8 rows -> 8 vector REDs
    // (was 32 scalar atomics; RED lane-issue cost /4).
    #pragma unroll
    for (int r = 0; r < 4; r++) {
        int p0 = ty * 8 + 2 * r;
        int o0 = sOut[p0];
        int o1 = sOut[p0 + 1];
        float lo0 = __uint_as_float((unsigned)(acc[r][0] & 0xffffffffULL));
        float lo1 = __uint_as_float((unsigned)(acc[r][1] & 0xffffffffULL));
        float lo2 = __uint_as_float((unsigned)(acc[r][2] & 0xffffffffULL));
        float lo3 = __uint_as_float((unsigned)(acc[r][3] & 0xffffffffULL));
        float hi0 = __uint_as_float((unsigned)(acc[r][0] >> 32));
        float hi1 = __uint_as_float((unsigned)(acc[r][1] >> 32));
        float hi2 = __uint_as_float((unsigned)(acc[r][2] >> 32));
        float hi3 = __uint_as_float((unsigned)(acc[r][3] >> 32));
        if (o0 >= 0) RED_V4(out + o0 * CCH + tx * 4, lo0, lo1, lo2, lo3);
        if (o1 >= 0) RED_V4(out + o1 * CCH + tx * 4, hi0, hi1, hi2, hi3);
    }
}

extern "C" void kernel_launch(void* const* d_in, const int* in_sizes, int n_in,
                              void* d_out, int out_size)
{
    const float* input  = (const float*)d_in[0];
    const float* kern   = (const float*)d_in[1];
    const float* bias   = (const float*)d_in[2];
    const int*   in_map = (const int*)  d_in[3];
    const int*   out_map= (const int*)  d_in[4];
    float* out = (float*)d_out;

    cudaFuncSetAttribute(sparse_conv_kernel,
                         cudaFuncAttributeMaxDynamicSharedMemorySize, SMEM_BYTES);

    // out = bias (d_out is poisoned before timing)
    init_bias_kernel<<<(NPTS * CCH + 255) / 256, 256>>>(bias, out);

    dim3 grid(NTILES, KVOL);
    sparse_conv_kernel<<<grid, 256, SMEM_BYTES>>>(input, kern, in_map, out_map, out);
}

// round 4
// speedup vs baseline: 1.7789x; 1.4273x over previous
#include <cuda_runtime.h>
#include <cstdint>

#define NPTS  100000
#define KVOL  27
#define PAIRS 60000
#define CCH   64
#define TP    128
#define NTILES ((PAIRS + TP - 1) / TP)

// smem: A 128x64 tf32 (swizzled rows of 256B) | B 64x64 tf32 (W^T, swizzled) | maps
#define SA_OFF 0
#define SB_OFF 32768
#define MAPS_OFF 49152
#define SMEM_BYTES 50176

#define RED_V2(ptr, x, y) \
    asm volatile("red.global.add.v2.f32 [%0], {%1,%2};" \
                 :: "l"(ptr), "f"(x), "f"(y) : "memory")

__device__ __forceinline__ uint32_t smem_u32(const void* p) {
    uint32_t a;
    asm("{ .reg .u64 t; cvta.to.shared.u64 t, %1; cvt.u32.u64 %0, t; }"
        : "=r"(a) : "l"(p));
    return a;
}

__device__ __forceinline__ uint32_t f2tf32(float f) {
    uint32_t r;
    asm("cvt.rna.tf32.f32 %0, %1;" : "=r"(r) : "f"(f));
    return r;
}

#define LDSM_X4(r0, r1, r2, r3, addr) \
    asm volatile("ldmatrix.sync.aligned.m8n8.x4.shared.b16 {%0,%1,%2,%3}, [%4];" \
                 : "=r"(r0), "=r"(r1), "=r"(r2), "=r"(r3) : "r"(addr))

#define MMA_TF32(c, a0, a1, a2, a3, b0, b1) \
    asm volatile("mma.sync.aligned.m16n8k8.row.col.f32.tf32.tf32.f32 " \
                 "{%0,%1,%2,%3}, {%4,%5,%6,%7}, {%8,%9}, {%0,%1,%2,%3};" \
                 : "+f"(c[0]), "+f"(c[1]), "+f"(c[2]), "+f"(c[3]) \
                 : "r"(a0), "r"(a1), "r"(a2), "r"(a3), "r"(b0), "r"(b1))

__global__ void __launch_bounds__(256) init_bias_kernel(
    const float* __restrict__ bias, float* __restrict__ out)
{
    int idx = blockIdx.x * 256 + threadIdx.x;
    if (idx < NPTS * CCH) out[idx] = bias[idx & (CCH - 1)];
}

// swizzled byte offset inside a 256B row: chunk' = k16 ^ (row & 7)
__device__ __forceinline__ uint32_t sw_off(int row, int k16) {
    return (uint32_t)(row * 256 + ((k16 ^ (row & 7)) << 4));
}

__global__ void __launch_bounds__(128, 4) sparse_conv_kernel(
    const float* __restrict__ input,
    const float* __restrict__ kernel,
    const int*   __restrict__ in_map,
    const int*   __restrict__ out_map,
    float*       __restrict__ out)
{
    extern __shared__ __align__(1024) char smem[];
    const uint32_t sb = smem_u32(smem);
    int* sIn  = (int*)(smem + MAPS_OFF);
    int* sOut = sIn + TP;

    const int k    = blockIdx.y;
    const int base = blockIdx.x * TP;
    const int tid  = threadIdx.x;
    const int w    = tid >> 5;
    const int l    = tid & 31;
    const int nrem = min(TP, PAIRS - base);

    // pair maps (coalesced)
    if (tid < nrem) {
        sIn[tid]  = in_map [k * PAIRS + base + tid];
        sOut[tid] = out_map[k * PAIRS + base + tid];
    } else {
        sIn[tid] = -1;
        sOut[tid] = -1;
    }
    __syncthreads();

    // ---- gather X -> sA (tf32, swizzled). 16 lanes cover one row:
    // coalesced 256B gmem reads, conflict-free STS.128 ----
    #pragma unroll
    for (int s = 0; s < 16; s++) {
        int m   = tid + 128 * s;
        int p   = m >> 4;
        int j16 = m & 15;
        int row = sIn[p];
        float4 v = make_float4(0.f, 0.f, 0.f, 0.f);
        if (row >= 0) v = ((const float4*)input)[row * (CCH / 4) + j16];
        uint4 t;
        t.x = f2tf32(v.x); t.y = f2tf32(v.y);
        t.z = f2tf32(v.z); t.w = f2tf32(v.w);
        *(uint4*)(smem + SA_OFF + sw_off(p, j16)) = t;
    }

    // ---- W_k -> sB as W^T[n][i] (row n = output channel, 64 tf32 over K).
    // Each thread: one (i, o4); lanes vary i -> conflict-free STS.32 ----
    {
        const float4* Wg = (const float4*)(kernel + k * CCH * CCH);
        #pragma unroll
        for (int s = 0; s < 8; s++) {
            int idx = tid + 128 * s;
            int i   = idx & 63;          // K index
            int o4  = idx >> 6;          // group of 4 output channels
            float4 v = Wg[i * 16 + o4];
            #pragma unroll
            for (int j = 0; j < 4; j++) {
                int n = o4 * 4 + j;
                float f = (j == 0) ? v.x : (j == 1) ? v.y : (j == 2) ? v.z : v.w;
                *(uint32_t*)(smem + SB_OFF + n * 256
                             + (((i >> 2) ^ (n & 7)) << 4) + (i & 3) * 4) = f2tf32(f);
            }
        }
    }
    __syncthreads();

    // ---- GEMM via mma.sync tf32: warp w computes rows [32w,32w+32) x 64 cols.
    // 2 m16 tiles x 8 n8 tiles, K=64 in 8 chunks of 8. ----
    float acc[2][8][4];
    #pragma unroll
    for (int mt = 0; mt < 2; mt++)
        #pragma unroll
        for (int nt = 0; nt < 8; nt++)
            #pragma unroll
            for (int c = 0; c < 4; c++) acc[mt][nt][c] = 0.f;

    // ldmatrix per-lane row assignments
    const int arow = 32 * w + (((l >> 3) & 1) << 3) + (l & 7);  // + 16*mt
    const int ahi  = l >> 4;                                    // k16 low bit
    const int asw  = arow & 7;
    const int brow = ((l >> 4) << 3) + (l & 7);                 // + n0
    const int bhi  = (l >> 3) & 1;
    const int bsw  = brow & 7;
    const uint32_t aBase = sb + SA_OFF + arow * 256;
    const uint32_t bBase = sb + SB_OFF + brow * 256;

    #pragma unroll
    for (int kk = 0; kk < 8; kk++) {
        uint32_t a[2][4];
        #pragma unroll
        for (int mt = 0; mt < 2; mt++) {
            uint32_t addr = aBase + mt * 4096 + ((((kk << 1) | ahi) ^ asw) << 4);
            LDSM_X4(a[mt][0], a[mt][1], a[mt][2], a[mt][3], addr);
        }
        uint32_t b[8][2];
        #pragma unroll
        for (int g = 0; g < 4; g++) {       // n0 = 16g, covers n-tiles 2g, 2g+1
            uint32_t r0, r1, r2, r3;
            uint32_t addr = bBase + g * 4096 + ((((kk << 1) | bhi) ^ bsw) << 4);
            LDSM_X4(r0, r1, r2, r3, addr);
            b[2 * g][0] = r0; b[2 * g][1] = r1;
            b[2 * g + 1][0] = r2; b[2 * g + 1][1] = r3;
        }
        #pragma unroll
        for (int mt = 0; mt < 2; mt++)
            #pragma unroll
            for (int nt = 0; nt < 8; nt++)
                MMA_TF32(acc[mt][nt], a[mt][0], a[mt][1], a[mt][2], a[mt][3],
                         b[nt][0], b[nt][1]);
    }

    // ---- scatter-add straight from fragments: red.v2 per (row, col-pair) ----
    #pragma unroll
    for (int mt = 0; mt < 2; mt++) {
        int R0 = 32 * w + 16 * mt + (l >> 2);
        int o0 = sOut[R0];
        int o1 = sOut[R0 + 8];
        int cbase = 2 * (l & 3);
        #pragma unroll
        for (int nt = 0; nt < 8; nt++) {
            int col = 8 * nt + cbase;
            if (o0 >= 0)
                RED_V2(out + o0 * CCH + col, acc[mt][nt][0], acc[mt][nt][1]);
            if (o1 >= 0)
                RED_V2(out + o1 * CCH + col, acc[mt][nt][2], acc[mt][nt][3]);
        }
    }
}

extern "C" void kernel_launch(void* const* d_in, const int* in_sizes, int n_in,
                              void* d_out, int out_size)
{
    const float* input  = (const float*)d_in[0];
    const float* kern   = (const float*)d_in[1];
    const float* bias   = (const float*)d_in[2];
    const int*   in_map = (const int*)  d_in[3];
    const int*   out_map= (const int*)  d_in[4];
    float* out = (float*)d_out;

    cudaFuncSetAttribute(sparse_conv_kernel,
                         cudaFuncAttributeMaxDynamicSharedMemorySize, SMEM_BYTES);

    init_bias_kernel<<<(NPTS * CCH + 255) / 256, 256>>>(bias, out);

    dim3 grid(NTILES, KVOL);
    sparse_conv_kernel<<<grid, 128, SMEM_BYTES>>>(input, kern, in_map, out_map, out);
}

// round 5
// speedup vs baseline: 1.7940x; 1.0085x over previous
#include <cuda_runtime.h>
#include <cstdint>

#define NPTS  100000
#define KVOL  27
#define PAIRS 60000
#define CCH   64
#define TP    128
#define NTILES ((PAIRS + TP - 1) / TP)

// smem: A 128x64 tf32 (swizzled rows of 256B) | B 64x64 tf32 (W^T, swizzled) | maps
#define SA_OFF 0
#define SB_OFF 32768
#define MAPS_OFF 49152
#define SMEM_BYTES 50176

#define RED_V4(ptr, x, y, z, w) \
    asm volatile("red.global.add.v4.f32 [%0], {%1,%2,%3,%4};" \
                 :: "l"(ptr), "f"(x), "f"(y), "f"(z), "f"(w) : "memory")

__device__ __forceinline__ uint32_t smem_u32(const void* p) {
    uint32_t a;
    asm("{ .reg .u64 t; cvta.to.shared.u64 t, %1; cvt.u32.u64 %0, t; }"
        : "=r"(a) : "l"(p));
    return a;
}

__device__ __forceinline__ uint32_t f2tf32(float f) {
    uint32_t r;
    asm("cvt.rna.tf32.f32 %0, %1;" : "=r"(r) : "f"(f));
    return r;
}

#define LDSM_X4(r0, r1, r2, r3, addr) \
    asm volatile("ldmatrix.sync.aligned.m8n8.x4.shared.b16 {%0,%1,%2,%3}, [%4];" \
                 : "=r"(r0), "=r"(r1), "=r"(r2), "=r"(r3) : "r"(addr))

#define MMA_TF32(c, a0, a1, a2, a3, b0, b1) \
    asm volatile("mma.sync.aligned.m16n8k8.row.col.f32.tf32.tf32.f32 " \
                 "{%0,%1,%2,%3}, {%4,%5,%6,%7}, {%8,%9}, {%0,%1,%2,%3};" \
                 : "+f"(c[0]), "+f"(c[1]), "+f"(c[2]), "+f"(c[3]) \
                 : "r"(a0), "r"(a1), "r"(a2), "r"(a3), "r"(b0), "r"(b1))

__global__ void __launch_bounds__(256) init_bias_kernel(
    const float* __restrict__ bias, float* __restrict__ out)
{
    int idx = blockIdx.x * 256 + threadIdx.x;
    if (idx < NPTS * CCH) out[idx] = bias[idx & (CCH - 1)];
}

// swizzled byte offset inside a 256B row: chunk' = k16 ^ (row & 7)
__device__ __forceinline__ uint32_t sw_off(int row, int k16) {
    return (uint32_t)(row * 256 + ((k16 ^ (row & 7)) << 4));
}

__global__ void __launch_bounds__(128, 4) sparse_conv_kernel(
    const float* __restrict__ input,
    const float* __restrict__ kernel,
    const int*   __restrict__ in_map,
    const int*   __restrict__ out_map,
    float*       __restrict__ out)
{
    extern __shared__ __align__(1024) char smem[];
    const uint32_t sb = smem_u32(smem);
    int* sIn  = (int*)(smem + MAPS_OFF);
    int* sOut = sIn + TP;

    const int k    = blockIdx.y;
    const int base = blockIdx.x * TP;
    const int tid  = threadIdx.x;
    const int w    = tid >> 5;
    const int l    = tid & 31;
    const int nrem = min(TP, PAIRS - base);

    // pair maps (coalesced)
    if (tid < nrem) {
        sIn[tid]  = in_map [k * PAIRS + base + tid];
        sOut[tid] = out_map[k * PAIRS + base + tid];
    } else {
        sIn[tid] = -1;
        sOut[tid] = -1;
    }
    __syncthreads();

    // ---- gather X -> sA (tf32, swizzled). 16 lanes cover one row:
    // coalesced 256B gmem reads, conflict-free STS.128 ----
    #pragma unroll
    for (int s = 0; s < 16; s++) {
        int m   = tid + 128 * s;
        int p   = m >> 4;
        int j16 = m & 15;
        int row = sIn[p];
        float4 v = make_float4(0.f, 0.f, 0.f, 0.f);
        if (row >= 0) v = ((const float4*)input)[row * (CCH / 4) + j16];
        uint4 t;
        t.x = f2tf32(v.x); t.y = f2tf32(v.y);
        t.z = f2tf32(v.z); t.w = f2tf32(v.w);
        *(uint4*)(smem + SA_OFF + sw_off(p, j16)) = t;
    }

    // ---- W_k -> sB as W^T[n][i] (row n = output channel, 64 tf32 over K) ----
    {
        const float4* Wg = (const float4*)(kernel + k * CCH * CCH);
        #pragma unroll
        for (int s = 0; s < 8; s++) {
            int idx = tid + 128 * s;
            int i   = idx & 63;          // K index
            int o4  = idx >> 6;          // group of 4 output channels
            float4 v = Wg[i * 16 + o4];
            #pragma unroll
            for (int j = 0; j < 4; j++) {
                int n = o4 * 4 + j;
                float f = (j == 0) ? v.x : (j == 1) ? v.y : (j == 2) ? v.z : v.w;
                *(uint32_t*)(smem + SB_OFF + n * 256
                             + (((i >> 2) ^ (n & 7)) << 4) + (i & 3) * 4) = f2tf32(f);
            }
        }
    }
    __syncthreads();

    // ---- GEMM via mma.sync tf32: warp w computes rows [32w,32w+32) x 64 cols ----
    float acc[2][8][4];
    #pragma unroll
    for (int mt = 0; mt < 2; mt++)
        #pragma unroll
        for (int nt = 0; nt < 8; nt++)
            #pragma unroll
            for (int c = 0; c < 4; c++) acc[mt][nt][c] = 0.f;

    const int arow = 32 * w + (((l >> 3) & 1) << 3) + (l & 7);  // + 16*mt
    const int ahi  = l >> 4;
    const int asw  = arow & 7;
    const int brow = ((l >> 4) << 3) + (l & 7);                 // + n0
    const int bhi  = (l >> 3) & 1;
    const int bsw  = brow & 7;
    const uint32_t aBase = sb + SA_OFF + arow * 256;
    const uint32_t bBase = sb + SB_OFF + brow * 256;

    #pragma unroll
    for (int kk = 0; kk < 8; kk++) {
        uint32_t a[2][4];
        #pragma unroll
        for (int mt = 0; mt < 2; mt++) {
            uint32_t addr = aBase + mt * 4096 + ((((kk << 1) | ahi) ^ asw) << 4);
            LDSM_X4(a[mt][0], a[mt][1], a[mt][2], a[mt][3], addr);
        }
        uint32_t b[8][2];
        #pragma unroll
        for (int g = 0; g < 4; g++) {
            uint32_t r0, r1, r2, r3;
            uint32_t addr = bBase + g * 4096 + ((((kk << 1) | bhi) ^ bsw) << 4);
            LDSM_X4(r0, r1, r2, r3, addr);
            b[2 * g][0] = r0; b[2 * g][1] = r1;
            b[2 * g + 1][0] = r2; b[2 * g + 1][1] = r3;
        }
        #pragma unroll
        for (int mt = 0; mt < 2; mt++)
            #pragma unroll
            for (int nt = 0; nt < 8; nt++)
                MMA_TF32(acc[mt][nt], a[mt][0], a[mt][1], a[mt][2], a[mt][3],
                         b[nt][0], b[nt][1]);
    }

    // ---- scatter-add: butterfly shfl (l^1) to assemble 4 consecutive cols
    // per lane, then ONE guarded red.v4 per (mt,nt).
    // even lane -> row r cols[cb..cb+3]; odd lane -> row r+8 cols[cb-2..cb+1].
    const int odd = l & 1;
    #pragma unroll
    for (int mt = 0; mt < 2; mt++) {
        int row = 32 * w + 16 * mt + (l >> 2) + (odd ? 8 : 0);
        int o   = sOut[row];
        int cb  = 2 * (l & 3) - (odd ? 2 : 0);
        #pragma unroll
        for (int nt = 0; nt < 8; nt++) {
            float s0 = odd ? acc[mt][nt][0] : acc[mt][nt][2];
            float s1 = odd ? acc[mt][nt][1] : acc[mt][nt][3];
            float r0 = __shfl_xor_sync(0xffffffffu, s0, 1);
            float r1 = __shfl_xor_sync(0xffffffffu, s1, 1);
            float v0 = odd ? r0 : acc[mt][nt][0];
            float v1 = odd ? r1 : acc[mt][nt][1];
            float v2 = odd ? acc[mt][nt][2] : r0;
            float v3 = odd ? acc[mt][nt][3] : r1;
            if (o >= 0)
                RED_V4(out + o * CCH + 8 * nt + cb, v0, v1, v2, v3);
        }
    }
}

extern "C" void kernel_launch(void* const* d_in, const int* in_sizes, int n_in,
                              void* d_out, int out_size)
{
    const float* input  = (const float*)d_in[0];
    const float* kern   = (const float*)d_in[1];
    const float* bias   = (const float*)d_in[2];
    const int*   in_map = (const int*)  d_in[3];
    const int*   out_map= (const int*)  d_in[4];
    float* out = (float*)d_out;

    cudaFuncSetAttribute(sparse_conv_kernel,
                         cudaFuncAttributeMaxDynamicSharedMemorySize, SMEM_BYTES);

    init_bias_kernel<<<(NPTS * CCH + 255) / 256, 256>>>(bias, out);

    dim3 grid(NTILES, KVOL);
    sparse_conv_kernel<<<grid, 128, SMEM_BYTES>>>(input, kern, in_map, out_map, out);
}